// round 11
// baseline (speedup 1.0000x reference)
#include <cuda_runtime.h>
#include <cstdint>
#include <cstddef>

// CTC loss (faithful to reference incl. input_len = C bug).
// B=512, T=512 (row stride), C=128, Tu=128, L=64, S=129, blank=127.
// TWO warps per row as a lagged wavefront pipeline:
//   W0 (role 0): states 0..63  (lane: 2l blank, 2l+1 label l)
//   W1 (role 1): states 64..128 (lane: 64+2l blank, 65+2l label 32+l; +128)
// Dependency flows upward only; W0 publishes state-63 per step into a 32-slot
// smem ring; W1 runs exactly one 8-step chunk behind. Both halves share W0's
// per-chunk power-of-2 rescale exponent (published via smem), so boundary
// values need one exact 2^k adjustment per chunk. Linear domain throughout.
// 8-warp blocks (4 rows) -> 128 blocks -> 2 warps/SMSP on 128 SMs.

#define B_    512
#define T_    512
#define C_    128
#define L_    64
#define BLANK 127
#define EPSF  (1e-7f)
#define LN2F  0.69314718055994530942f

#define ROWS   4
#define CHUNK  8
#define NBUF   4
#define NCHUNK 16
#define STG_F  (ROWS * NBUF * CHUNK * C_)    // 16384 floats = 64 KB
#define BND_F  (ROWS * 32)
#define E0_I   (ROWS * 4)
#define SMEM_BYTES ((STG_F + BND_F) * 4 + E0_I * 4)

__device__ __forceinline__ void cpasync16(uint32_t saddr, const void* g) {
    asm volatile("cp.async.cg.shared.global [%0], [%1], 16;" :: "r"(saddr), "l"(g));
}
__device__ __forceinline__ void cp_commit() { asm volatile("cp.async.commit_group;"); }
__device__ __forceinline__ void cp_wait2()  { asm volatile("cp.async.wait_group 2;"); }

__device__ __forceinline__ int redux_max(int v) {
    int r; asm volatile("redux.sync.max.s32 %0, %1, 0xffffffff;" : "=r"(r) : "r"(v));
    return r;
}
__device__ __forceinline__ float exp2i(int k) {   // 2^k, |k| <= 126
    return __int_as_float((127 + k) << 23);
}

__global__ __launch_bounds__(ROWS * 64, 1)
void ctc_kernel(const int* __restrict__ y_true,
                const float* __restrict__ y_pred,
                float* __restrict__ out)
{
    extern __shared__ float sm[];
    float* stg = sm;                          // [ROWS][NBUF][CHUNK][C_]
    float* bnd = sm + STG_F;                  // [ROWS][32] boundary ring
    int*   e0r = (int*)(bnd + BND_F);         // [ROWS][4] W0 chunk exponents

    const unsigned FULL = 0xffffffffu;
    const int tid  = threadIdx.x;
    const int lane = tid & 31;
    const int w    = tid >> 5;
    const int r    = w >> 1;                  // row within block
    const int role = w & 1;                   // 0 = lower half, 1 = upper half
    const int b    = blockIdx.x * ROWS + r;

    float* mystg = stg + (size_t)r * NBUF * CHUNK * C_;
    float* mybnd = bnd + r * 32;
    int*   mye0  = e0r + r * 4;
    const uint32_t smbase = (uint32_t)__cvta_generic_to_shared(mystg);

    const float* __restrict__ row = y_pred + (size_t)b * T_ * C_;
    const int*   __restrict__ lab = y_true + b * L_;

    // per-lane label + skip flag: odd state 2*li+1 carries label li
    const int li = role * 32 + lane;
    const int l  = lab[li];
    const float sk = (li > 0 && l != lab[li - 1]) ? 1.f : 0.f;

    auto issue_chunk = [&](int c) {           // role 0 only
        const float* g = row + (size_t)c * CHUNK * C_ + lane * 4;
        const uint32_t s = smbase +
            (uint32_t)(((c & (NBUF - 1)) * CHUNK * C_ + lane * 4) * 4);
        #pragma unroll
        for (int j = 0; j < CHUNK; ++j)
            cpasync16(s + j * C_ * 4, g + j * C_);
    };

    // init boundary ring + exponent ring
    for (int i = tid; i < BND_F; i += ROWS * 64) bnd[i] = 0.f;
    for (int i = tid; i < E0_I;  i += ROWS * 64) e0r[i] = 0;

    // ---- state: aA = even(blank) state, aB = odd(label) state ---------------
    float aA = (role == 0 && lane == 0) ? 1.f : 0.f;   // virtual init
    float aB = 0.f;
    float a4 = 0.f;                                    // state 128 (W1 lane31)
    int etot = 0;

    if (role == 0) {
        issue_chunk(0); cp_commit();
        issue_chunk(1); cp_commit();
    }
    __syncthreads();     // smem init + visibility baseline

    for (int it = 0; it <= NCHUNK; ++it) {
        if (role == 0) {
            if (it + 2 < NCHUNK) issue_chunk(it + 2);
            cp_commit();
            if (it < NCHUNK) cp_wait2();
        }
        __syncthreads();   // prev iter's bnd/e0 + this iter's staging visible

        if (role == 0) {
            if (it < NCHUNK) {
                const int c = it;
                const float* srow = mystg + (size_t)(c & (NBUF - 1)) * CHUNK * C_;
                #pragma unroll
                for (int j = 0; j < CHUNK; ++j) {
                    const float qB = srow[j * C_ + BLANK] + EPSF;
                    const float qL = srow[j * C_ + l]     + EPSF;
                    const float t  = __shfl_up_sync(FULL, aB, 1);
                    const float n1 = (lane == 0) ? 0.f : t;
                    const float naA = (aA + n1) * qB;
                    const float naB = fmaf(sk, n1, aB + aA) * qL;
                    aA = naA; aB = naB;
                    if (lane == 31)
                        mybnd[(c * CHUNK + j + 1) & 31] = aB;   // state 63 @ t
                }
                // power-of-two rescale; publish exponent
                const int rb = redux_max(__float_as_int(fmaxf(aA, aB)));
                int e = (rb >> 23) - 127;
                if (rb == 0) e = 0;
                const float sc = exp2i(-e);
                aA *= sc; aB *= sc;
                if (lane == 0) mye0[c & 3] = e;
            }
        } else {
            if (it >= 1) {
                const int c = it - 1;
                const float* srow = mystg + (size_t)(c & (NBUF - 1)) * CHUNK * C_;
                // boundary values alpha_{t-1}[63] for t = 8c..8c+7
                float bv[CHUNK];
                #pragma unroll
                for (int j = 0; j < CHUNK; ++j)
                    bv[j] = mybnd[(c * CHUNK + j) & 31];
                // first element originates from W0's previous chunk scale:
                // multiply by 2^{-e0[c-1]} (split to stay in exp2i range)
                {
                    const int adj = -mye0[(c - 1) & 3];
                    const int h1 = adj / 2, h2 = adj - h1;
                    bv[0] = bv[0] * exp2i(h1) * exp2i(h2);
                }
                #pragma unroll
                for (int j = 0; j < CHUNK; ++j) {
                    const float qB = srow[j * C_ + BLANK] + EPSF;
                    const float qL = srow[j * C_ + l]     + EPSF;
                    const float t  = __shfl_up_sync(FULL, aB, 1);
                    const float n1 = (lane == 0) ? bv[j] : t;
                    const float naA = (aA + n1) * qB;
                    const float naB = fmaf(sk, n1, aB + aA) * qL;
                    const float na4 = (a4 + aB) * qB;     // state 128 (lane31)
                    aA = naA; aB = naB; a4 = na4;
                }
                // rescale with W0's exponent for this chunk (exact 2^k)
                const int e = mye0[c & 3];
                const float sc = exp2i(-e);
                aA *= sc; aB *= sc; a4 *= sc;
                etot += e;
            }
        }
    }

    // ---- loss = -( ln(alpha[127] + alpha[128]) + etot*ln2 ) ------------------
    if (role == 1 && lane == 31) {
        const float s = aB + a4;              // states 127 (aB), 128 (a4)
        out[b] = -(__logf(s) + (float)etot * LN2F);
    }
}

extern "C" void kernel_launch(void* const* d_in, const int* in_sizes, int n_in,
                              void* d_out, int out_size)
{
    const int* y_true;
    const float* y_pred;
    if (n_in >= 2 && in_sizes[0] == B_ * L_) {
        y_true = (const int*)d_in[0];
        y_pred = (const float*)d_in[1];
    } else {
        y_true = (const int*)d_in[1];
        y_pred = (const float*)d_in[0];
    }
    float* out = (float*)d_out;

    cudaFuncSetAttribute(ctc_kernel,
                         cudaFuncAttributeMaxDynamicSharedMemorySize, SMEM_BYTES);

    // 128 blocks x 256 threads (4 rows x 2 warps) -> 2 warps/SMSP on 128 SMs
    ctc_kernel<<<B_ / ROWS, ROWS * 64, SMEM_BYTES>>>(y_true, y_pred, out);
}

// round 12
// speedup vs baseline: 1.3789x; 1.3789x over previous
#include <cuda_runtime.h>
#include <cstdint>
#include <cstddef>

// CTC loss (faithful to reference incl. input_len = C bug).
// B=512, T=512 (row stride), C=128, Tu=128, L=64, S=129, blank=127.
// One 32-thread block per batch row (512 blocks -> best measured shape).
// Lane holds states 4*lane+j (j=0..3), lane31 also state 128.
// Linear domain, power-of-2 rescale per 8 steps, 128 uniform steps from
// virtual init a0=1@lane0. eps dropped (<=1.6e-3 abs on ~600-magnitude loss).
// ENTIRE 128-step loop fully unrolled: no branches, no BSSY/BSYNC, free
// cross-step scheduling. cp.async staging (4-buffer ring, depth 3).

#define B_    512
#define T_    512
#define C_    128
#define L_    64
#define BLANK 127
#define LN2F  0.69314718055994530942f

#define CHUNK  8
#define NBUF   4
#define NCHUNK 16

__device__ __forceinline__ void cpasync16(uint32_t saddr, const void* g) {
    asm volatile("cp.async.cg.shared.global [%0], [%1], 16;" :: "r"(saddr), "l"(g));
}
__device__ __forceinline__ void cp_commit() { asm volatile("cp.async.commit_group;"); }
__device__ __forceinline__ void cp_wait2()  { asm volatile("cp.async.wait_group 2;"); }
__device__ __forceinline__ void cp_wait0()  { asm volatile("cp.async.wait_group 0;"); }

__device__ __forceinline__ float lds(uint32_t addr) {
    float v; asm volatile("ld.shared.f32 %0, [%1];" : "=f"(v) : "r"(addr));
    return v;
}

__global__ __launch_bounds__(32)
void ctc_kernel(const int* __restrict__ y_true,
                const float* __restrict__ y_pred,
                float* __restrict__ out)
{
    __shared__ float sm[NBUF][CHUNK][C_];
    const unsigned FULL = 0xffffffffu;
    const int lane = threadIdx.x & 31;
    const int b    = blockIdx.x;

    const uint32_t smb = (uint32_t)__cvta_generic_to_shared(&sm[0][0][0]);
    const float* __restrict__ row = y_pred + (size_t)b * T_ * C_;

    // labels (coalesced int2): lane -> labels 2*lane, 2*lane+1
    const int2 lpair = ((const int2*)(y_true + b * L_))[lane];
    const int l0 = lpair.x, l1 = lpair.y;
    const int lp = __shfl_up_sync(FULL, l1, 1);
    const bool sk1 = (lane > 0) && (l0 != lp);   // state 4l+1 skip
    const bool sk3 = (l1 != l0);                 // state 4l+3 skip

    // precomputed LDS base addresses (per-lane constants)
    const uint32_t ad0 = smb + (uint32_t)l0 * 4u;
    const uint32_t ad1 = smb + (uint32_t)l1 * 4u;
    const uint32_t adB = smb + (uint32_t)BLANK * 4u;

    // staging source pointer (per-lane)
    const float* gsrc = row + lane * 4;

    // ---- alpha state: virtual init => 128 uniform steps ---------------------
    float a0 = (lane == 0) ? 1.f : 0.f;
    float a1 = 0.f, a2 = 0.f, a3 = 0.f, a4 = 0.f;
    float n3 = 0.f;
    int etot = 0;

    // ---- prologue: stage chunks 0..2 -----------------------------------------
    #pragma unroll
    for (int k = 0; k < 3; ++k) {
        #pragma unroll
        for (int j = 0; j < CHUNK; ++j)
            cpasync16(smb + (uint32_t)((k * CHUNK + j) * C_ + lane * 4) * 4u,
                      gsrc + (size_t)(k * CHUNK + j) * C_);
        cp_commit();
    }

    // ---- fully unrolled main loop: 16 chunks x 8 steps -----------------------
    #pragma unroll
    for (int c = 0; c < NCHUNK; ++c) {
        // stage chunk c+3 (compile-time guard -> no runtime branch)
        if (c + 3 < NCHUNK) {
            const int cc = c + 3;
            #pragma unroll
            for (int j = 0; j < CHUNK; ++j)
                cpasync16(smb + (uint32_t)(((cc & (NBUF - 1)) * CHUNK + j) * C_
                                           + lane * 4) * 4u,
                          gsrc + (size_t)(cc * CHUNK + j) * C_);
            cp_commit();
            cp_wait2();
        } else {
            cp_wait0();
        }
        __syncwarp();

        const uint32_t boff = (uint32_t)((c & (NBUF - 1)) * CHUNK * C_) * 4u;

        #pragma unroll
        for (int j = 0; j < CHUNK; ++j) {
            const uint32_t so = boff + (uint32_t)(j * C_) * 4u;
            const float q0 = lds(ad0 + so);
            const float q1 = lds(ad1 + so);
            const float qB = lds(adB + so);

            const float n3s = sk1 ? n3 : 0.f;            // SELP
            const float a1s = sk3 ? a1 : 0.f;            // SELP

            const float na3 = (a3 + a2 + a1s) * q1;      // early: feeds shfl
            const float t   = __shfl_up_sync(FULL, na3, 1);

            const float na0 = (a0 + n3) * qB;
            const float na1 = (a1 + a0 + n3s) * q0;
            const float na2 = (a2 + a1) * qB;
            const float na4 = (a4 + a3) * qB;

            a0 = na0; a1 = na1; a2 = na2; a3 = na3; a4 = na4;
            n3 = (lane == 0) ? 0.f : t;
        }

        // power-of-two rescale (alpha >= 0 -> float bits monotonic as s32)
        float mv = fmaxf(fmaxf(a0, a1), fmaxf(fmaxf(a2, a3), a4));
        int rb;
        asm volatile("redux.sync.max.s32 %0, %1, 0xffffffff;"
                     : "=r"(rb) : "r"(__float_as_int(mv)));
        const int e = (rb >> 23) - 127;
        const float sc = __int_as_float((127 - e) << 23);      // 2^-e
        a0 *= sc; a1 *= sc; a2 *= sc; a3 *= sc; a4 *= sc; n3 *= sc;
        etot += e;
    }

    // ---- loss = -( ln(alpha[127] + alpha[128]) + etot*ln2 ) ------------------
    if (lane == 31) {
        const float s = a3 + a4;          // states 127, 128
        out[b] = -(__logf(s) + (float)etot * LN2F);
    }
}

extern "C" void kernel_launch(void* const* d_in, const int* in_sizes, int n_in,
                              void* d_out, int out_size)
{
    const int* y_true;
    const float* y_pred;
    if (n_in >= 2 && in_sizes[0] == B_ * L_) {
        y_true = (const int*)d_in[0];
        y_pred = (const float*)d_in[1];
    } else {
        y_true = (const int*)d_in[1];
        y_pred = (const float*)d_in[0];
    }
    float* out = (float*)d_out;

    ctc_kernel<<<B_, 32>>>(y_true, y_pred, out);
}

// round 13
// speedup vs baseline: 1.6204x; 1.1752x over previous
#include <cuda_runtime.h>
#include <cstdint>
#include <cstddef>

// CTC loss (faithful to reference incl. input_len = C bug).
// B=512, T=512 (row stride), C=128, Tu=128, L=64, S=129, blank=127.
// FORWARD/BACKWARD SPLIT: one 64-thread block per row, 2 warps.
//   Warp A (role 0): forward alpha, t = 0..63   (64 serial steps)
//   Warp B (role 1): backward C_t(s)=q_t(s)*(C(s)+C(s+1)+skip(s)C(s+2)),
//                    t = 127..64, in reversed coords tau = 128-s, which makes
//                    the body IDENTICAL to the forward one (same shfl_up,
//                    same virtual init) with remapped labels/skips.
// Combine: P = sum_s preA_64(s) * C_64(s) (129-term dot via smem + reduce).
// Linear domain, power-of-2 rescale per 8 steps (per-warp exponent, summed
// at the end). eps dropped (rel effect ~4e-6, threshold 1e-3).
// Fully unrolled 8-chunk loops, cp.async staging per warp.

#define B_    512
#define T_    512
#define C_    128
#define L_    64
#define BLANK 127
#define LN2F  0.69314718055994530942f

#define CHUNK  8
#define NBUF   4
#define NCHUNK_H 8          // 64 timesteps per warp

__device__ __forceinline__ void cpasync16(uint32_t saddr, const void* g) {
    asm volatile("cp.async.cg.shared.global [%0], [%1], 16;" :: "r"(saddr), "l"(g));
}
__device__ __forceinline__ void cp_commit() { asm volatile("cp.async.commit_group;"); }
__device__ __forceinline__ void cp_wait2()  { asm volatile("cp.async.wait_group 2;"); }
__device__ __forceinline__ void cp_wait0()  { asm volatile("cp.async.wait_group 0;"); }

__device__ __forceinline__ float lds(uint32_t addr) {
    float v; asm volatile("ld.shared.f32 %0, [%1];" : "=f"(v) : "r"(addr));
    return v;
}

__global__ __launch_bounds__(64)
void ctc_kernel(const int* __restrict__ y_true,
                const float* __restrict__ y_pred,
                float* __restrict__ out)
{
    __shared__ float stg[2][NBUF][CHUNK][C_];   // per-warp staging (32 KB)
    __shared__ float xch[132];                  // C_64 by state s (129 used)
    __shared__ int   etB_sh;

    const unsigned FULL = 0xffffffffu;
    const int lane = threadIdx.x & 31;
    const int role = threadIdx.x >> 5;          // 0 = forward, 1 = backward
    const int b    = blockIdx.x;

    const uint32_t smb = (uint32_t)__cvta_generic_to_shared(&stg[role][0][0][0]);
    const float* __restrict__ row = y_pred + (size_t)b * T_ * C_;
    const int2* labp = (const int2*)(y_true + b * L_);

    // ---- per-lane classes / skip flags --------------------------------------
    int cls0, cls1;          // class for odd state j=1, j=3 (this lane)
    bool sk1, sk3;
    if (role == 0) {
        const int2 lp = labp[lane];               // lab[2l], lab[2l+1]
        cls0 = lp.x; cls1 = lp.y;
        const int prev = __shfl_up_sync(FULL, lp.y, 1);   // lab[2l-1]
        sk1 = (lane > 0) && (cls0 != prev);
        sk3 = (cls1 != cls0);
    } else {
        const int2 lp = labp[31 - lane];          // .x=lab[62-2l], .y=lab[63-2l]
        cls0 = lp.y;                              // tau=4l+1 -> lab[63-2l]
        cls1 = lp.x;                              // tau=4l+3 -> lab[62-2l]
        const int nb = __shfl_up_sync(FULL, lp.x, 1);     // lab[64-2l] (lane-1 .x)
        sk1 = (lane > 0) && (nb != cls0);         // lab[64-2l] != lab[63-2l]
        sk3 = (cls0 != cls1);                     // lab[63-2l] != lab[62-2l]
    }
    const uint32_t ad0 = smb + (uint32_t)cls0 * 4u;
    const uint32_t ad1 = smb + (uint32_t)cls1 * 4u;
    const uint32_t adB = smb + (uint32_t)BLANK * 4u;

    // staging: role 0 -> rows t = 8c..8c+7 ; role 1 -> rows t = 120-8c..127-8c
    // backward buffer stores rows in ASCENDING t; step j consumes slot (7-j).
    const float* gsrc = row + lane * 4;

    // ---- alpha / C state: virtual init (identical shape both roles) ---------
    float a0 = (lane == 0) ? 1.f : 0.f;
    float a1 = 0.f, a2 = 0.f, a3 = 0.f, a4 = 0.f;
    float n3 = 0.f;
    int etot = 0;

    // ---- prologue: stage chunks 0..2 -----------------------------------------
    #pragma unroll
    for (int k = 0; k < 3; ++k) {
        const int t0 = (role == 0) ? (k * CHUNK) : (120 - k * CHUNK);
        #pragma unroll
        for (int j = 0; j < CHUNK; ++j)
            cpasync16(smb + (uint32_t)((k * CHUNK + j) * C_ + lane * 4) * 4u,
                      gsrc + (size_t)(t0 + j) * C_);
        cp_commit();
    }

    // ---- fully unrolled main loop: 8 chunks x 8 steps -------------------------
    #pragma unroll
    for (int c = 0; c < NCHUNK_H; ++c) {
        if (c + 3 < NCHUNK_H) {
            const int cc = c + 3;
            const int t0 = (role == 0) ? (cc * CHUNK) : (120 - cc * CHUNK);
            #pragma unroll
            for (int j = 0; j < CHUNK; ++j)
                cpasync16(smb + (uint32_t)(((cc & (NBUF - 1)) * CHUNK + j) * C_
                                           + lane * 4) * 4u,
                          gsrc + (size_t)(t0 + j) * C_);
            cp_commit();
            cp_wait2();
        } else {
            cp_wait0();
        }
        __syncwarp();

        const uint32_t boff = (uint32_t)((c & (NBUF - 1)) * CHUNK * C_) * 4u;

        #pragma unroll
        for (int j = 0; j < CHUNK; ++j) {
            const int slot = (role == 0) ? j : (7 - j);   // backward walks down
            const uint32_t so = boff + (uint32_t)(slot * C_) * 4u;
            const float q0 = lds(ad0 + so);
            const float q1 = lds(ad1 + so);
            const float qB = lds(adB + so);

            const float n3s = sk1 ? n3 : 0.f;
            const float a1s = sk3 ? a1 : 0.f;

            const float na3 = (a3 + a2 + a1s) * q1;
            const float t   = __shfl_up_sync(FULL, na3, 1);

            const float na0 = (a0 + n3) * qB;
            const float na1 = (a1 + a0 + n3s) * q0;
            const float na2 = (a2 + a1) * qB;
            const float na4 = (a4 + a3) * qB;

            a0 = na0; a1 = na1; a2 = na2; a3 = na3; a4 = na4;
            n3 = (lane == 0) ? 0.f : t;
        }

        // power-of-two rescale (alpha >= 0 -> float bits monotonic as s32)
        float mv = fmaxf(fmaxf(a0, a1), fmaxf(fmaxf(a2, a3), a4));
        int rb;
        asm volatile("redux.sync.max.s32 %0, %1, 0xffffffff;"
                     : "=r"(rb) : "r"(__float_as_int(mv)));
        const int e = (rb >> 23) - 127;
        const float sc = __int_as_float((127 - e) << 23);
        a0 *= sc; a1 *= sc; a2 *= sc; a3 *= sc; a4 *= sc; n3 *= sc;
        etot += e;
    }

    // ---- combine --------------------------------------------------------------
    if (role == 1) {
        // after 64 iterations we hold C_64 in tau layout; write by state s=128-tau
        xch[128 - (4 * lane + 0)] = a0;
        xch[128 - (4 * lane + 1)] = a1;
        xch[128 - (4 * lane + 2)] = a2;
        xch[128 - (4 * lane + 3)] = a3;
        if (lane == 31) { xch[0] = a4; etB_sh = etot; }   // tau=128 -> s=0
    }
    __syncthreads();

    if (role == 0) {
        // pre-sums of step t=64 WITHOUT the q multiply (alpha_64 / q_64)
        const float n3s = sk1 ? n3 : 0.f;
        const float a1s = sk3 ? a1 : 0.f;
        const float p0 = a0 + n3;
        const float p1 = a1 + a0 + n3s;
        const float p2 = a2 + a1;
        const float p3 = a3 + a2 + a1s;
        const float p4 = a4 + a3;

        float dot = p0 * xch[4 * lane + 0]
                  + p1 * xch[4 * lane + 1]
                  + p2 * xch[4 * lane + 2]
                  + p3 * xch[4 * lane + 3];
        if (lane == 31) dot += p4 * xch[128];

        #pragma unroll
        for (int k = 16; k >= 1; k >>= 1)
            dot += __shfl_xor_sync(FULL, dot, k);

        if (lane == 0)
            out[b] = -(__logf(dot) + (float)(etot + etB_sh) * LN2F);
    }
}

extern "C" void kernel_launch(void* const* d_in, const int* in_sizes, int n_in,
                              void* d_out, int out_size)
{
    const int* y_true;
    const float* y_pred;
    if (n_in >= 2 && in_sizes[0] == B_ * L_) {
        y_true = (const int*)d_in[0];
        y_pred = (const float*)d_in[1];
    } else {
        y_true = (const int*)d_in[1];
        y_pred = (const float*)d_in[0];
    }
    float* out = (float*)d_out;

    ctc_kernel<<<B_, 64>>>(y_true, y_pred, out);
}

// round 14
// speedup vs baseline: 1.6567x; 1.0224x over previous
#include <cuda_runtime.h>
#include <cstdint>
#include <cstddef>

// CTC loss (faithful to reference incl. input_len = C bug).
// B=512, T=512 (row stride), C=128, Tu=128, L=64, S=129, blank=127.
// FORWARD/BACKWARD SPLIT (validated R13): one 64-thread block per row.
//   Warp A (role 0): forward alpha, t = 0..63
//   Warp B (role 1): backward completion in reversed coords (identical body)
// Combine: P = sum_s preA_64(s) * C_64(s).
// Round 14 change: DEEP up-front staging. 6 buffers/warp; prologue issues all
// 6 chunks (24 KB/warp in flight), chunks 6-7 reuse buffers 0-1. Compile-time
// wait_group immediates {5,5,5,4,3,2,1,0}; steady loop has no exposed waits.
// 48.6 KB smem/block (dynamic) -> 4 blocks/SM -> 592 slots >= 512: one wave.

#define B_    512
#define T_    512
#define C_    128
#define L_    64
#define BLANK 127
#define LN2F  0.69314718055994530942f

#define CHUNK  8
#define NBUF   6
#define NCH    8            // 64 timesteps per warp

__device__ __forceinline__ void cpasync16(uint32_t saddr, const void* g) {
    asm volatile("cp.async.cg.shared.global [%0], [%1], 16;" :: "r"(saddr), "l"(g));
}
__device__ __forceinline__ void cp_commit() { asm volatile("cp.async.commit_group;"); }
template <int N>
__device__ __forceinline__ void cp_wait() {
    asm volatile("cp.async.wait_group %0;" :: "n"(N));
}
__device__ __forceinline__ float lds(uint32_t addr) {
    float v; asm volatile("ld.shared.f32 %0, [%1];" : "=f"(v) : "r"(addr));
    return v;
}

#define STG_F (2 * NBUF * CHUNK * C_)         // 12288 floats = 48 KB
#define SMEM_BYTES (STG_F * 4 + 132 * 4 + 16)

__global__ __launch_bounds__(64)
void ctc_kernel(const int* __restrict__ y_true,
                const float* __restrict__ y_pred,
                float* __restrict__ out)
{
    extern __shared__ float smem_dyn[];
    float* stg  = smem_dyn;                   // [2][NBUF][CHUNK][C_]
    float* xch  = smem_dyn + STG_F;           // [132] C_64 by state s
    int*   etBp = (int*)(xch + 132);

    const unsigned FULL = 0xffffffffu;
    const int lane = threadIdx.x & 31;
    const int role = threadIdx.x >> 5;        // 0 = forward, 1 = backward
    const int b    = blockIdx.x;

    const uint32_t smb = (uint32_t)__cvta_generic_to_shared(
        stg + (size_t)role * NBUF * CHUNK * C_);
    const float* __restrict__ row = y_pred + (size_t)b * T_ * C_;
    const int2* labp = (const int2*)(y_true + b * L_);

    // ---- per-lane classes / skip flags (R13-validated mapping) ---------------
    int cls0, cls1;
    bool sk1, sk3;
    if (role == 0) {
        const int2 lp = labp[lane];                        // lab[2l], lab[2l+1]
        cls0 = lp.x; cls1 = lp.y;
        const int prev = __shfl_up_sync(FULL, lp.y, 1);    // lab[2l-1]
        sk1 = (lane > 0) && (cls0 != prev);
        sk3 = (cls1 != cls0);
    } else {
        const int2 lp = labp[31 - lane];                   // lab[62-2l], lab[63-2l]
        cls0 = lp.y;
        cls1 = lp.x;
        const int nb = __shfl_up_sync(FULL, lp.x, 1);      // lab[64-2l]
        sk1 = (lane > 0) && (nb != cls0);
        sk3 = (cls0 != cls1);
    }
    const uint32_t ad0 = smb + (uint32_t)cls0 * 4u;
    const uint32_t ad1 = smb + (uint32_t)cls1 * 4u;
    const uint32_t adB = smb + (uint32_t)BLANK * 4u;

    const float* gsrc = row + lane * 4;

    // ---- alpha / C state (identical shape both roles) ------------------------
    float a0 = (lane == 0) ? 1.f : 0.f;
    float a1 = 0.f, a2 = 0.f, a3 = 0.f, a4 = 0.f;
    float n3 = 0.f;
    int etot = 0;

    // ---- staging helper: chunk cc -> buffer bb -------------------------------
    auto stage = [&](int cc, int bb) {
        const int t0 = (role == 0) ? (cc * CHUNK) : (120 - cc * CHUNK);
        #pragma unroll
        for (int j = 0; j < CHUNK; ++j)
            cpasync16(smb + (uint32_t)((bb * CHUNK + j) * C_ + lane * 4) * 4u,
                      gsrc + (size_t)(t0 + j) * C_);
        cp_commit();
    };

    // ---- compute helper: 8 steps from buffer bb + rescale --------------------
    auto compute = [&](int bb) {
        const uint32_t boff = (uint32_t)(bb * CHUNK * C_) * 4u;
        #pragma unroll
        for (int j = 0; j < CHUNK; ++j) {
            const int slot = (role == 0) ? j : (7 - j);    // backward walks down
            const uint32_t so = boff + (uint32_t)(slot * C_) * 4u;
            const float q0 = lds(ad0 + so);
            const float q1 = lds(ad1 + so);
            const float qB = lds(adB + so);

            const float n3s = sk1 ? n3 : 0.f;
            const float a1s = sk3 ? a1 : 0.f;

            const float na3 = (a3 + a2 + a1s) * q1;
            const float t   = __shfl_up_sync(FULL, na3, 1);

            const float na0 = (a0 + n3) * qB;
            const float na1 = (a1 + a0 + n3s) * q0;
            const float na2 = (a2 + a1) * qB;
            const float na4 = (a4 + a3) * qB;

            a0 = na0; a1 = na1; a2 = na2; a3 = na3; a4 = na4;
            n3 = (lane == 0) ? 0.f : t;
        }
        float mv = fmaxf(fmaxf(a0, a1), fmaxf(fmaxf(a2, a3), a4));
        int rb;
        asm volatile("redux.sync.max.s32 %0, %1, 0xffffffff;"
                     : "=r"(rb) : "r"(__float_as_int(mv)));
        const int e = (rb >> 23) - 127;
        const float sc = __int_as_float((127 - e) << 23);  // 2^-e
        a0 *= sc; a1 *= sc; a2 *= sc; a3 *= sc; a4 *= sc; n3 *= sc;
        etot += e;
    };

    // ---- prologue: issue ALL 6 buffered chunks (24 KB/warp in flight) --------
    #pragma unroll
    for (int k = 0; k < NBUF; ++k) stage(k, k);

    // ---- steady sequence, compile-time wait immediates ------------------------
    cp_wait<5>(); __syncwarp(); compute(0); stage(6, 0);   // chunk 0; refill buf0
    cp_wait<5>(); __syncwarp(); compute(1); stage(7, 1);   // chunk 1; refill buf1
    cp_wait<5>(); __syncwarp(); compute(2);
    cp_wait<4>(); __syncwarp(); compute(3);
    cp_wait<3>(); __syncwarp(); compute(4);
    cp_wait<2>(); __syncwarp(); compute(5);
    cp_wait<1>(); __syncwarp(); compute(0);                // chunk 6 (buf0)
    cp_wait<0>(); __syncwarp(); compute(1);                // chunk 7 (buf1)

    // ---- combine ---------------------------------------------------------------
    if (role == 1) {
        xch[128 - (4 * lane + 0)] = a0;
        xch[128 - (4 * lane + 1)] = a1;
        xch[128 - (4 * lane + 2)] = a2;
        xch[128 - (4 * lane + 3)] = a3;
        if (lane == 31) { xch[0] = a4; *etBp = etot; }     // tau=128 -> s=0
    }
    __syncthreads();

    if (role == 0) {
        const float n3s = sk1 ? n3 : 0.f;
        const float a1s = sk3 ? a1 : 0.f;
        const float p0 = a0 + n3;
        const float p1 = a1 + a0 + n3s;
        const float p2 = a2 + a1;
        const float p3 = a3 + a2 + a1s;
        const float p4 = a4 + a3;

        float dot = p0 * xch[4 * lane + 0]
                  + p1 * xch[4 * lane + 1]
                  + p2 * xch[4 * lane + 2]
                  + p3 * xch[4 * lane + 3];
        if (lane == 31) dot += p4 * xch[128];

        #pragma unroll
        for (int k = 16; k >= 1; k >>= 1)
            dot += __shfl_xor_sync(FULL, dot, k);

        if (lane == 0)
            out[b] = -(__logf(dot) + (float)(etot + *etBp) * LN2F);
    }
}

extern "C" void kernel_launch(void* const* d_in, const int* in_sizes, int n_in,
                              void* d_out, int out_size)
{
    const int* y_true;
    const float* y_pred;
    if (n_in >= 2 && in_sizes[0] == B_ * L_) {
        y_true = (const int*)d_in[0];
        y_pred = (const float*)d_in[1];
    } else {
        y_true = (const int*)d_in[1];
        y_pred = (const float*)d_in[0];
    }
    float* out = (float*)d_out;

    cudaFuncSetAttribute(ctc_kernel,
                         cudaFuncAttributeMaxDynamicSharedMemorySize, SMEM_BYTES);

    ctc_kernel<<<B_, 64, SMEM_BYTES>>>(y_true, y_pred, out);
}